// round 16
// baseline (speedup 1.0000x reference)
#include <cuda_runtime.h>
#include <cuda_fp16.h>
#include <cstdint>

#define BETA   0.95f
#define THRESH 1.0f

constexpr int NI = 80, NH = 256, NC = 2, T = 200, BATCH = 4096;
constexpr int NB = 32, NBLK = BATCH / NB, NTHR = 512;   // 16 warps, j-tile 16

// Per-warp A-frag stream (dedup'd): L1: 10 (kc0..4 x {hi,lo}), L2: 32, L3: 32
constexpr int FPW = 74, L2BASE = 10, L3BASE = 42;
__device__ __align__(16) __half g_wfrag[16 * FPW * 256];   // 606 KB, L2-resident

// LDS.64-conflict-free strides: word-stride mod 32 == 8
constexpr int SKX = 80;
constexpr int SKS = 272;
constexpr int SXSZ = 32 * SKX;   // one x buffer (halfs)

// k-interleave within each 16-k block: (k, k+8) adjacent -> one LDS.64 per B frag
__host__ __device__ __forceinline__ int fintl(int kk) {
    return ((kk & 6) << 1) | (kk & 1) | ((kk & 8) >> 2);
}

// ---- prep: pack split weights into m16n8k16 A-frag lane order ----
__global__ void prep(const float* __restrict__ W1, const float* __restrict__ W2,
                     const float* __restrict__ W3) {
    int idx = blockIdx.x * 256 + threadIdx.x;      // 16*74*256
    if (idx >= 16 * FPW * 256) return;
    int h = idx & 7;
    int l = (idx >> 3) & 31;
    int f = (idx >> 8) % FPW;
    int w = (idx >> 8) / FPW;
    const float* W; int K, kc, split;
    if (f < L2BASE)      { kc = f >> 1; split = f & 1; W = W1; K = NI; }
    else if (f < L3BASE) { int g = f - L2BASE; kc = g >> 1; split = g & 1; W = W2; K = NH; }
    else                 { int g = f - L3BASE; kc = g >> 1; split = g & 1; W = W3; K = NH; }
    int r = (l >> 2) + ((h >> 1) & 1) * 8;
    int k = (l & 3) * 2 + (h & 1) + ((h >> 2) & 1) * 8;
    int j = w * 16 + r;
    int i = kc * 16 + k;
    float v = W[j * K + i];
    __half hv = __float2half_rn(v);
    if (split) hv = __float2half_rn(v - __half2float(hv));
    g_wfrag[idx] = hv;
}

__device__ __forceinline__ void mma16816(float* d, uint4 a, uint32_t b0, uint32_t b1) {
    asm volatile(
        "mma.sync.aligned.m16n8k16.row.col.f32.f16.f16.f32 "
        "{%0,%1,%2,%3}, {%4,%5,%6,%7}, {%8,%9}, {%0,%1,%2,%3};"
        : "+f"(d[0]), "+f"(d[1]), "+f"(d[2]), "+f"(d[3])
        : "r"(a.x), "r"(a.y), "r"(a.z), "r"(a.w), "r"(b0), "r"(b1));
}

// L2/L3: D[16j x 32b] += Wsplit * spikes. Depth-1 A-prefetch (round-12 form).
__device__ __forceinline__ void gemm256(const __half* __restrict__ sB,
                                        const uint4* __restrict__ ab, int base,
                                        float acc[4][4], int l, uint4 a0, uint4 a1) {
    const int q4 = (l & 3) * 4, rw = (l >> 2);
#pragma unroll
    for (int kc = 0; kc < 16; kc++) {
        uint4 n0, n1;
        if (kc < 15) {
            n0 = ab[(base + 2 * kc + 2) * 32 + l];
            n1 = ab[(base + 2 * kc + 3) * 32 + l];
        }
        uint2 bf[4];
#pragma unroll
        for (int nt = 0; nt < 4; nt++)
            bf[nt] = *(const uint2*)(sB + (nt * 8 + rw) * SKS + kc * 16 + q4);
#pragma unroll
        for (int nt = 0; nt < 4; nt++) mma16816(acc[nt], a0, bf[nt].x, bf[nt].y);
#pragma unroll
        for (int nt = 0; nt < 4; nt++) mma16816(acc[nt], a1, bf[nt].x, bf[nt].y);
        a0 = n0; a1 = n1;
    }
}

// L1: products hiW*hiX, hiW*loX, loW*hiX over K=80 (hi frag reused in-register)
__device__ __forceinline__ void gemm80(const __half* __restrict__ sXhi,
                                       const __half* __restrict__ sXlo,
                                       const uint4* __restrict__ ab,
                                       float acc[4][4], int l, uint4 ah, uint4 al) {
    const int q4 = (l & 3) * 4, rw = (l >> 2);
#pragma unroll
    for (int kc = 0; kc < 5; kc++) {
        uint4 nh, nl;
        if (kc < 4) {
            nh = ab[(2 * kc + 2) * 32 + l];
            nl = ab[(2 * kc + 3) * 32 + l];
        }
        uint2 bh[4], bl[4];
#pragma unroll
        for (int nt = 0; nt < 4; nt++) {
            int off = (nt * 8 + rw) * SKX + kc * 16 + q4;
            bh[nt] = *(const uint2*)(sXhi + off);
            bl[nt] = *(const uint2*)(sXlo + off);
        }
#pragma unroll
        for (int nt = 0; nt < 4; nt++) mma16816(acc[nt], ah, bh[nt].x, bh[nt].y);
#pragma unroll
        for (int nt = 0; nt < 4; nt++) mma16816(acc[nt], ah, bl[nt].x, bl[nt].y);
#pragma unroll
        for (int nt = 0; nt < 4; nt++) mma16816(acc[nt], al, bh[nt].x, bh[nt].y);
        ah = nh; al = nl;
    }
}

// Stage 4 timesteps of x into the 4-deep SMEM ring (interleaved positions).
__device__ __forceinline__ void stage_x4(const float* __restrict__ x, __half* sX,
                                         int b0, int t0, int start, int stride) {
    for (int k = start; k < NI * NB; k += stride) {
        int b = k / NI, i = k - b * NI;
        float4 v = *(const float4*)(x + ((size_t)(b0 + b) * NI + i) * T + t0);
        float vv[4] = { v.x, v.y, v.z, v.w };
        int off = b * SKX + (i >> 4) * 16 + fintl(i & 15);
#pragma unroll
        for (int tt = 0; tt < 4; tt++) {
            __half hh = __float2half_rn(vv[tt]);
            __half hl = __float2half_rn(vv[tt] - __half2float(hh));
            sX[(tt * 2 + 0) * SXSZ + off] = hh;
            sX[(tt * 2 + 1) * SXSZ + off] = hl;
        }
    }
}

__global__ void __launch_bounds__(NTHR) snn_kernel(
    const float* __restrict__ x,
    const float* __restrict__ B1, const float* __restrict__ B2,
    const float* __restrict__ B3, const float* __restrict__ W4,
    const float* __restrict__ b4, float* __restrict__ out)
{
    extern __shared__ __align__(16) char smem[];
    __half* sX   = (__half*)smem;                  // [4 tt][2 hi/lo][32*80]
    __half* sS1  = sX + 8 * SXSZ;                  // 32*272
    __half* sS2  = sS1 + 32 * SKS;
    float*  s3f  = (float*)(sS2 + 32 * SKS);       // [256 j][33]
    float*  w4s  = s3f + 256 * 33;                 // 512

    const int tid = threadIdx.x, l = tid & 31, w = tid >> 5;
    const int b0 = blockIdx.x * NB;
    const int jw = w * 16;
    const uint4* ab = ((const uint4*)g_wfrag) + (size_t)w * FPW * 32;

    int fj[2];
    {
        int r = l >> 2;
        fj[0] = ((r & 6) << 1) | (r & 1);
        fj[1] = fj[0] + 2;
    }

    float bias1[2], bias2[2], bias3[2];
#pragma unroll
    for (int rh = 0; rh < 2; rh++) {
        int j = jw + (l >> 2) + rh * 8;
        bias1[rh] = B1[j]; bias2[rh] = B2[j]; bias3[rh] = B3[j];
    }

    float m1[4][4], m2[4][4], m3[4][4];
#pragma unroll
    for (int nt = 0; nt < 4; nt++)
#pragma unroll
        for (int d = 0; d < 4; d++) { m1[nt][d] = 0.f; m2[nt][d] = 0.f; m3[nt][d] = 0.f; }

    float m4v = 0.f, b4v = 0.f;
    if (tid < NB * NC) b4v = b4[tid & 1];
    for (int k = tid; k < NC * NH; k += NTHR) w4s[k] = W4[k];

    float acc[4][4];

    // ---- prologue: stage x(0..3); L1(0); L2(0) ----
    stage_x4(x, sX, b0, 0, tid, NTHR);
    uint4 p0 = ab[0 * 32 + l], p1 = ab[1 * 32 + l];
    __syncthreads();

#pragma unroll
    for (int nt = 0; nt < 4; nt++)
#pragma unroll
        for (int d = 0; d < 4; d++) acc[nt][d] = 0.f;
    gemm80(sX, sX + SXSZ, ab, acc, l, p0, p1);
#pragma unroll
    for (int nt = 0; nt < 4; nt++)
#pragma unroll
        for (int d = 0; d < 4; d++) {
            int rh = d >> 1, c = d & 1;
            float cur = acc[nt][d] + bias1[rh];
            float mo = m1[nt][d];
            float mn = BETA * mo + cur - ((mo > THRESH) ? THRESH : 0.0f);
            m1[nt][d] = mn;
            int b = nt * 8 + (l & 3) * 2 + c;
            sS1[b * SKS + jw + fj[rh]] =
                (mn > THRESH) ? __ushort_as_half((unsigned short)0x3C00)
                              : __ushort_as_half((unsigned short)0);
        }
    p0 = ab[L2BASE * 32 + l]; p1 = ab[(L2BASE + 1) * 32 + l];
    __syncthreads();

#pragma unroll
    for (int nt = 0; nt < 4; nt++)
#pragma unroll
        for (int d = 0; d < 4; d++) acc[nt][d] = 0.f;
    gemm256(sS1, ab, L2BASE, acc, l, p0, p1);
#pragma unroll
    for (int nt = 0; nt < 4; nt++)
#pragma unroll
        for (int d = 0; d < 4; d++) {
            int rh = d >> 1, c = d & 1;
            float cur = acc[nt][d] + bias2[rh];
            float mo = m2[nt][d];
            float mn = BETA * mo + cur - ((mo > THRESH) ? THRESH : 0.0f);
            m2[nt][d] = mn;
            int b = nt * 8 + (l & 3) * 2 + c;
            sS2[b * SKS + jw + fj[rh]] =
                (mn > THRESH) ? __ushort_as_half((unsigned short)0x3C00)
                              : __ushort_as_half((unsigned short)0);
        }
    p0 = ab[L3BASE * 32 + l]; p1 = ab[(L3BASE + 1) * 32 + l];
    __syncthreads();

    // ---- steady state: 2 phases (2 barriers) per step ----
    for (int t = 0; t < T; t++) {
        // Phase A: L3(t), then L1(t+1)
#pragma unroll
        for (int nt = 0; nt < 4; nt++)
#pragma unroll
            for (int d = 0; d < 4; d++) acc[nt][d] = 0.f;
        gemm256(sS2, ab, L3BASE, acc, l, p0, p1);
#pragma unroll
        for (int nt = 0; nt < 4; nt++)
#pragma unroll
            for (int d = 0; d < 4; d++) {
                int rh = d >> 1, c = d & 1;
                float cur = acc[nt][d] + bias3[rh];
                float mo = m3[nt][d];
                float mn = BETA * mo + cur - ((mo > THRESH) ? THRESH : 0.0f);
                m3[nt][d] = mn;
                int j = jw + (l >> 2) + rh * 8;
                int b = nt * 8 + (l & 3) * 2 + c;
                s3f[j * 33 + b] = (mn > THRESH) ? 1.0f : 0.0f;
            }
        if (t + 1 < T) {
            const __half* sXhi = sX + (((t + 1) & 3) * 2) * SXSZ;
            const __half* sXlo = sXhi + SXSZ;
#pragma unroll
            for (int nt = 0; nt < 4; nt++)
#pragma unroll
                for (int d = 0; d < 4; d++) acc[nt][d] = 0.f;
            gemm80(sXhi, sXlo, ab, acc, l, ab[0 * 32 + l], ab[1 * 32 + l]);
#pragma unroll
            for (int nt = 0; nt < 4; nt++)
#pragma unroll
                for (int d = 0; d < 4; d++) {
                    int rh = d >> 1, c = d & 1;
                    float cur = acc[nt][d] + bias1[rh];
                    float mo = m1[nt][d];
                    float mn = BETA * mo + cur - ((mo > THRESH) ? THRESH : 0.0f);
                    m1[nt][d] = mn;
                    int b = nt * 8 + (l & 3) * 2 + c;
                    sS1[b * SKS + jw + fj[rh]] =
                        (mn > THRESH) ? __ushort_as_half((unsigned short)0x3C00)
                                      : __ushort_as_half((unsigned short)0);
                }
        }
        p0 = ab[L2BASE * 32 + l]; p1 = ab[(L2BASE + 1) * 32 + l];
        __syncthreads();

        // Phase B: L2(t+1) + L4(t) + x-staging
        if (t + 1 < T) {
#pragma unroll
            for (int nt = 0; nt < 4; nt++)
#pragma unroll
                for (int d = 0; d < 4; d++) acc[nt][d] = 0.f;
            gemm256(sS1, ab, L2BASE, acc, l, p0, p1);
#pragma unroll
            for (int nt = 0; nt < 4; nt++)
#pragma unroll
                for (int d = 0; d < 4; d++) {
                    int rh = d >> 1, c = d & 1;
                    float cur = acc[nt][d] + bias2[rh];
                    float mo = m2[nt][d];
                    float mn = BETA * mo + cur - ((mo > THRESH) ? THRESH : 0.0f);
                    m2[nt][d] = mn;
                    int b = nt * 8 + (l & 3) * 2 + c;
                    sS2[b * SKS + jw + fj[rh]] =
                        (mn > THRESH) ? __ushort_as_half((unsigned short)0x3C00)
                                      : __ushort_as_half((unsigned short)0);
                }
        }
        if (tid < NB * NC) {
            int b = tid >> 1, c = tid & 1;
            const float* sr = s3f + b;
            const float* wr = w4s + c * NH;
            float a0 = b4v, a1 = 0.f, a2 = 0.f, a3 = 0.f;
#pragma unroll 8
            for (int i = 0; i < NH; i += 4) {
                a0 = fmaf(sr[(i + 0) * 33], wr[i + 0], a0);
                a1 = fmaf(sr[(i + 1) * 33], wr[i + 1], a1);
                a2 = fmaf(sr[(i + 2) * 33], wr[i + 2], a2);
                a3 = fmaf(sr[(i + 3) * 33], wr[i + 3], a3);
            }
            float cur = (a0 + a1) + (a2 + a3);
            float mo = m4v;
            float mn = BETA * mo + cur - ((mo > THRESH) ? THRESH : 0.0f);
            m4v = mn;
            out[(size_t)t * (BATCH * NC) + b0 * NC + tid] = (mn > THRESH) ? 1.0f : 0.0f;
        } else if ((t & 3) == 2 && t + 2 < T) {
            // stage x(t+2..t+5); (t+2)%4==0 so slots align. x(t+1) (slot 3)
            // was consumed in Phase A of this iteration, barrier separates.
            stage_x4(x, sX, b0, t + 2, tid - 64, NTHR - 64);
        }
        p0 = ab[L3BASE * 32 + l]; p1 = ab[(L3BASE + 1) * 32 + l];
        __syncthreads();
    }
}

extern "C" void kernel_launch(void* const* d_in, const int* in_sizes, int n_in,
                              void* d_out, int out_size) {
    const float* x  = (const float*)d_in[0];
    const float* W1 = (const float*)d_in[1];
    const float* b1 = (const float*)d_in[2];
    const float* W2 = (const float*)d_in[3];
    const float* b2 = (const float*)d_in[4];
    const float* W3 = (const float*)d_in[5];
    const float* b3 = (const float*)d_in[6];
    const float* W4 = (const float*)d_in[7];
    const float* b4 = (const float*)d_in[8];
    float* out = (float*)d_out;

    prep<<<(16 * FPW * 256 + 255) / 256, 256>>>(W1, W2, W3);

    const int smem_bytes = (8 * SXSZ + 2 * 32 * SKS) * 2
                         + (256 * 33 + NC * NH) * 4;
    cudaFuncSetAttribute(snn_kernel,
                         cudaFuncAttributeMaxDynamicSharedMemorySize, smem_bytes);
    snn_kernel<<<NBLK, NTHR, smem_bytes>>>(x, b1, b2, b3, W4, b4, out);
}

// round 17
// speedup vs baseline: 1.1293x; 1.1293x over previous
#include <cuda_runtime.h>
#include <cuda_fp16.h>
#include <cstdint>

#define BETA   0.95f
#define THRESH 1.0f

constexpr int NI = 80, NH = 256, NC = 2, T = 200, BATCH = 4096;
constexpr int NB = 32, NBLK = BATCH / NB, NTHR = 512;   // 16 warps, j-tile 16

// Per-warp A-frag stream (dedup'd): L1: 10 (kc0..4 x {hi,lo}), L2: 32, L3: 32
constexpr int FPW = 74, L2BASE = 10, L3BASE = 42;
__device__ __align__(16) __half g_wfrag[16 * FPW * 256];   // 606 KB, L2-resident

// LDS.64-conflict-free strides: word-stride mod 32 == 8
constexpr int SKX = 80;
constexpr int SKS = 272;
constexpr int SXSZ = 32 * SKX;   // one x buffer (halfs)

// k-interleave within each 16-k block: (k, k+8) adjacent -> one LDS.64 per B frag
__host__ __device__ __forceinline__ int fintl(int kk) {
    return ((kk & 6) << 1) | (kk & 1) | ((kk & 8) >> 2);
}

// ---- prep: pack split weights into m16n8k16 A-frag lane order ----
__global__ void prep(const float* __restrict__ W1, const float* __restrict__ W2,
                     const float* __restrict__ W3) {
    int idx = blockIdx.x * 256 + threadIdx.x;      // 16*74*256
    if (idx >= 16 * FPW * 256) return;
    int h = idx & 7;
    int l = (idx >> 3) & 31;
    int f = (idx >> 8) % FPW;
    int w = (idx >> 8) / FPW;
    const float* W; int K, kc, split;
    if (f < L2BASE)      { kc = f >> 1; split = f & 1; W = W1; K = NI; }
    else if (f < L3BASE) { int g = f - L2BASE; kc = g >> 1; split = g & 1; W = W2; K = NH; }
    else                 { int g = f - L3BASE; kc = g >> 1; split = g & 1; W = W3; K = NH; }
    int r = (l >> 2) + ((h >> 1) & 1) * 8;
    int k = (l & 3) * 2 + (h & 1) + ((h >> 2) & 1) * 8;
    int j = w * 16 + r;
    int i = kc * 16 + k;
    float v = W[j * K + i];
    __half hv = __float2half_rn(v);
    if (split) hv = __float2half_rn(v - __half2float(hv));
    g_wfrag[idx] = hv;
}

__device__ __forceinline__ void mma16816(float* d, uint4 a, uint32_t b0, uint32_t b1) {
    asm volatile(
        "mma.sync.aligned.m16n8k16.row.col.f32.f16.f16.f32 "
        "{%0,%1,%2,%3}, {%4,%5,%6,%7}, {%8,%9}, {%0,%1,%2,%3};"
        : "+f"(d[0]), "+f"(d[1]), "+f"(d[2]), "+f"(d[3])
        : "r"(a.x), "r"(a.y), "r"(a.z), "r"(a.w), "r"(b0), "r"(b1));
}

// L2/L3 PAIR: one A-frag stream drives both timesteps' B tiles.
// Per-output accumulation order (fixed nt, per t): a0 then a1 per ascending kc
// -> bit-identical to the single-step version.
__device__ __forceinline__ void gemm256p(const __half* __restrict__ sB0,
                                         const __half* __restrict__ sB1,
                                         const uint4* __restrict__ ab, int base,
                                         float acc0[4][4], float acc1[4][4],
                                         int l, uint4 a0, uint4 a1) {
    const int q4 = (l & 3) * 4, rw = (l >> 2);
#pragma unroll
    for (int kc = 0; kc < 16; kc++) {
        uint4 n0, n1;
        if (kc < 15) {
            n0 = ab[(base + 2 * kc + 2) * 32 + l];
            n1 = ab[(base + 2 * kc + 3) * 32 + l];
        }
#pragma unroll
        for (int nt = 0; nt < 4; nt++) {
            uint2 b0 = *(const uint2*)(sB0 + (nt * 8 + rw) * SKS + kc * 16 + q4);
            uint2 b1 = *(const uint2*)(sB1 + (nt * 8 + rw) * SKS + kc * 16 + q4);
            mma16816(acc0[nt], a0, b0.x, b0.y);
            mma16816(acc0[nt], a1, b0.x, b0.y);
            mma16816(acc1[nt], a0, b1.x, b1.y);
            mma16816(acc1[nt], a1, b1.x, b1.y);
        }
        a0 = n0; a1 = n1;
    }
}

// L1 PAIR over K=80: per t the order is ah*bh, ah*bl, al*bh (as in round 12).
__device__ __forceinline__ void gemm80p(const __half* __restrict__ sXa,
                                        const __half* __restrict__ sXb,
                                        const uint4* __restrict__ ab,
                                        float acc0[4][4], float acc1[4][4],
                                        int l, uint4 ah, uint4 al) {
    const int q4 = (l & 3) * 4, rw = (l >> 2);
#pragma unroll
    for (int kc = 0; kc < 5; kc++) {
        uint4 nh, nl;
        if (kc < 4) {
            nh = ab[(2 * kc + 2) * 32 + l];
            nl = ab[(2 * kc + 3) * 32 + l];
        }
#pragma unroll
        for (int nt = 0; nt < 4; nt++) {
            int off = (nt * 8 + rw) * SKX + kc * 16 + q4;
            uint2 bh0 = *(const uint2*)(sXa + off);
            uint2 bl0 = *(const uint2*)(sXa + SXSZ + off);
            uint2 bh1 = *(const uint2*)(sXb + off);
            uint2 bl1 = *(const uint2*)(sXb + SXSZ + off);
            mma16816(acc0[nt], ah, bh0.x, bh0.y);
            mma16816(acc0[nt], ah, bl0.x, bl0.y);
            mma16816(acc0[nt], al, bh0.x, bh0.y);
            mma16816(acc1[nt], ah, bh1.x, bh1.y);
            mma16816(acc1[nt], ah, bl1.x, bl1.y);
            mma16816(acc1[nt], al, bh1.x, bh1.y);
        }
        ah = nh; al = nl;
    }
}

// Stage 4 timesteps of x (t0 % 4 == 0) into the 8-deep SMEM ring.
__device__ __forceinline__ void stage_x4(const float* __restrict__ x, __half* sX,
                                         int b0, int t0, int start, int stride) {
    for (int k = start; k < NI * NB; k += stride) {
        int b = k / NI, i = k - b * NI;
        float4 v = *(const float4*)(x + ((size_t)(b0 + b) * NI + i) * T + t0);
        float vv[4] = { v.x, v.y, v.z, v.w };
        int off = b * SKX + (i >> 4) * 16 + fintl(i & 15);
#pragma unroll
        for (int tt = 0; tt < 4; tt++) {
            int slot = (t0 + tt) & 7;
            __half hh = __float2half_rn(vv[tt]);
            __half hl = __float2half_rn(vv[tt] - __half2float(hh));
            sX[(slot * 2 + 0) * SXSZ + off] = hh;
            sX[(slot * 2 + 1) * SXSZ + off] = hl;
        }
    }
}

__global__ void __launch_bounds__(NTHR) snn_kernel(
    const float* __restrict__ x,
    const float* __restrict__ B1, const float* __restrict__ B2,
    const float* __restrict__ B3, const float* __restrict__ W4,
    const float* __restrict__ b4, float* __restrict__ out)
{
    extern __shared__ __align__(16) char smem[];
    __half* sX   = (__half*)smem;                  // [8 slots][2 hi/lo][32*80]
    __half* sS1a = sX + 16 * SXSZ;                 // 32*272 each
    __half* sS1b = sS1a + 32 * SKS;
    __half* sS2a = sS1b + 32 * SKS;
    __half* sS2b = sS2a + 32 * SKS;
    __half* s3a  = sS2b + 32 * SKS;                // [256 j][33] halfs
    __half* s3b  = s3a + 256 * 33;
    float*  w4s  = (float*)(s3b + 256 * 33 + 2);   // 512 floats (align pad)

    const int tid = threadIdx.x, l = tid & 31, w = tid >> 5;
    const int b0 = blockIdx.x * NB;
    const int jw = w * 16;
    const uint4* ab = ((const uint4*)g_wfrag) + (size_t)w * FPW * 32;

    int fj[2];
    {
        int r = l >> 2;
        fj[0] = ((r & 6) << 1) | (r & 1);
        fj[1] = fj[0] + 2;
    }

    float bias1[2], bias2[2], bias3[2];
#pragma unroll
    for (int rh = 0; rh < 2; rh++) {
        int j = jw + (l >> 2) + rh * 8;
        bias1[rh] = B1[j]; bias2[rh] = B2[j]; bias3[rh] = B3[j];
    }

    float m1[4][4], m2[4][4], m3[4][4];
#pragma unroll
    for (int nt = 0; nt < 4; nt++)
#pragma unroll
        for (int d = 0; d < 4; d++) { m1[nt][d] = 0.f; m2[nt][d] = 0.f; m3[nt][d] = 0.f; }

    float m4v = 0.f, b4v = 0.f;
    if (tid < NB * NC) b4v = b4[tid & 1];
    for (int k = tid; k < NC * NH; k += NTHR) w4s[k] = W4[k];

    stage_x4(x, sX, b0, 0, tid, NTHR);
    uint4 p0 = ab[0 * 32 + l], p1 = ab[1 * 32 + l];   // L1 kc=0/hi-lo
    __syncthreads();

    for (int tp = 0; tp < T; tp += 2) {
        float acc0[4][4], acc1[4][4];
        const __half* sXa = sX + ((tp & 7) * 2) * SXSZ;
        const __half* sXb = sX + (((tp + 1) & 7) * 2) * SXSZ;

        // ---- Phase 1: L1(tp) + L1(tp+1) ----
#pragma unroll
        for (int nt = 0; nt < 4; nt++)
#pragma unroll
            for (int d = 0; d < 4; d++) { acc0[nt][d] = 0.f; acc1[nt][d] = 0.f; }
        gemm80p(sXa, sXb, ab, acc0, acc1, l, p0, p1);
#pragma unroll
        for (int nt = 0; nt < 4; nt++)
#pragma unroll
            for (int d = 0; d < 4; d++) {
                int rh = d >> 1, c = d & 1;
                int b = nt * 8 + (l & 3) * 2 + c;
                float mo = m1[nt][d];
                float mn = BETA * mo + (acc0[nt][d] + bias1[rh])
                         - ((mo > THRESH) ? THRESH : 0.0f);
                sS1a[b * SKS + jw + fj[rh]] =
                    (mn > THRESH) ? __ushort_as_half((unsigned short)0x3C00)
                                  : __ushort_as_half((unsigned short)0);
                float mo2 = mn;
                mn = BETA * mo2 + (acc1[nt][d] + bias1[rh])
                   - ((mo2 > THRESH) ? THRESH : 0.0f);
                m1[nt][d] = mn;
                sS1b[b * SKS + jw + fj[rh]] =
                    (mn > THRESH) ? __ushort_as_half((unsigned short)0x3C00)
                                  : __ushort_as_half((unsigned short)0);
            }
        p0 = ab[L2BASE * 32 + l]; p1 = ab[(L2BASE + 1) * 32 + l];
        __syncthreads();

        // ---- Phase 2: L2 pair ----
#pragma unroll
        for (int nt = 0; nt < 4; nt++)
#pragma unroll
            for (int d = 0; d < 4; d++) { acc0[nt][d] = 0.f; acc1[nt][d] = 0.f; }
        gemm256p(sS1a, sS1b, ab, L2BASE, acc0, acc1, l, p0, p1);
#pragma unroll
        for (int nt = 0; nt < 4; nt++)
#pragma unroll
            for (int d = 0; d < 4; d++) {
                int rh = d >> 1, c = d & 1;
                int b = nt * 8 + (l & 3) * 2 + c;
                float mo = m2[nt][d];
                float mn = BETA * mo + (acc0[nt][d] + bias2[rh])
                         - ((mo > THRESH) ? THRESH : 0.0f);
                sS2a[b * SKS + jw + fj[rh]] =
                    (mn > THRESH) ? __ushort_as_half((unsigned short)0x3C00)
                                  : __ushort_as_half((unsigned short)0);
                float mo2 = mn;
                mn = BETA * mo2 + (acc1[nt][d] + bias2[rh])
                   - ((mo2 > THRESH) ? THRESH : 0.0f);
                m2[nt][d] = mn;
                sS2b[b * SKS + jw + fj[rh]] =
                    (mn > THRESH) ? __ushort_as_half((unsigned short)0x3C00)
                                  : __ushort_as_half((unsigned short)0);
            }
        p0 = ab[L3BASE * 32 + l]; p1 = ab[(L3BASE + 1) * 32 + l];
        __syncthreads();

        // ---- Phase 3: L3 pair ----
#pragma unroll
        for (int nt = 0; nt < 4; nt++)
#pragma unroll
            for (int d = 0; d < 4; d++) { acc0[nt][d] = 0.f; acc1[nt][d] = 0.f; }
        gemm256p(sS2a, sS2b, ab, L3BASE, acc0, acc1, l, p0, p1);
#pragma unroll
        for (int nt = 0; nt < 4; nt++)
#pragma unroll
            for (int d = 0; d < 4; d++) {
                int rh = d >> 1, c = d & 1;
                int j = jw + (l >> 2) + rh * 8;
                int b = nt * 8 + (l & 3) * 2 + c;
                float mo = m3[nt][d];
                float mn = BETA * mo + (acc0[nt][d] + bias3[rh])
                         - ((mo > THRESH) ? THRESH : 0.0f);
                s3a[j * 33 + b] = (mn > THRESH) ? __ushort_as_half((unsigned short)0x3C00)
                                                : __ushort_as_half((unsigned short)0);
                float mo2 = mn;
                mn = BETA * mo2 + (acc1[nt][d] + bias3[rh])
                   - ((mo2 > THRESH) ? THRESH : 0.0f);
                m3[nt][d] = mn;
                s3b[j * 33 + b] = (mn > THRESH) ? __ushort_as_half((unsigned short)0x3C00)
                                                : __ushort_as_half((unsigned short)0);
            }
        p0 = ab[0 * 32 + l]; p1 = ab[1 * 32 + l];   // L1 frags of next pair
        __syncthreads();

        // ---- Phase 4: L4 for both steps (tid<64); x-staging (tid>=64) ----
        if (tid < NB * NC) {
            int b = tid >> 1, c = tid & 1;
            const __half* sra = s3a + b;
            const __half* srb = s3b + b;
            const float* wr = w4s + c * NH;
            float a0 = b4v, a1 = 0.f, a2 = 0.f, a3 = 0.f;
            float e0 = b4v, e1 = 0.f, e2 = 0.f, e3 = 0.f;
#pragma unroll 8
            for (int i = 0; i < NH; i += 4) {
                a0 = fmaf(__half2float(sra[(i + 0) * 33]), wr[i + 0], a0);
                a1 = fmaf(__half2float(sra[(i + 1) * 33]), wr[i + 1], a1);
                a2 = fmaf(__half2float(sra[(i + 2) * 33]), wr[i + 2], a2);
                a3 = fmaf(__half2float(sra[(i + 3) * 33]), wr[i + 3], a3);
                e0 = fmaf(__half2float(srb[(i + 0) * 33]), wr[i + 0], e0);
                e1 = fmaf(__half2float(srb[(i + 1) * 33]), wr[i + 1], e1);
                e2 = fmaf(__half2float(srb[(i + 2) * 33]), wr[i + 2], e2);
                e3 = fmaf(__half2float(srb[(i + 3) * 33]), wr[i + 3], e3);
            }
            float cur0 = (a0 + a1) + (a2 + a3);
            float cur1 = (e0 + e1) + (e2 + e3);
            float mo = m4v;
            float mn = BETA * mo + cur0 - ((mo > THRESH) ? THRESH : 0.0f);
            out[(size_t)tp * (BATCH * NC) + b0 * NC + tid] = (mn > THRESH) ? 1.0f : 0.0f;
            float mo2 = mn;
            mn = BETA * mo2 + cur1 - ((mo2 > THRESH) ? THRESH : 0.0f);
            m4v = mn;
            out[(size_t)(tp + 1) * (BATCH * NC) + b0 * NC + tid] = (mn > THRESH) ? 1.0f : 0.0f;
        } else if ((tp & 3) == 0 && tp + 4 < T) {
            stage_x4(x, sX, b0, tp + 4, tid - 64, NTHR - 64);
        }
        __syncthreads();
    }
}

extern "C" void kernel_launch(void* const* d_in, const int* in_sizes, int n_in,
                              void* d_out, int out_size) {
    const float* x  = (const float*)d_in[0];
    const float* W1 = (const float*)d_in[1];
    const float* b1 = (const float*)d_in[2];
    const float* W2 = (const float*)d_in[3];
    const float* b2 = (const float*)d_in[4];
    const float* W3 = (const float*)d_in[5];
    const float* b3 = (const float*)d_in[6];
    const float* W4 = (const float*)d_in[7];
    const float* b4 = (const float*)d_in[8];
    float* out = (float*)d_out;

    prep<<<(16 * FPW * 256 + 255) / 256, 256>>>(W1, W2, W3);

    const int smem_bytes = (16 * SXSZ + 4 * 32 * SKS + 2 * 256 * 33 + 2) * 2
                         + (NC * NH) * 4;
    cudaFuncSetAttribute(snn_kernel,
                         cudaFuncAttributeMaxDynamicSharedMemorySize, smem_bytes);
    snn_kernel<<<NBLK, NTHR, smem_bytes>>>(x, b1, b2, b3, W4, b4, out);
}